// round 12
// baseline (speedup 1.0000x reference)
#include <cuda_runtime.h>
#include <cuda_fp16.h>
#include <math.h>
#include <stdint.h>

#define BB 64
#define LL 512
#define DD 512

// ---------------- scratch (no cudaMalloc allowed) ----------------
#define NTOT (32768ull * 512ull)
__device__ __half g_Xh[2*NTOT], g_Xl[2*NTOT];
__device__ __half g_Fh_[2*NTOT], g_Fl_[2*NTOT];
__device__ __half g_BTh[2*NTOT], g_BTl[2*NTOT];
__device__ __half g_ah[2*NTOT], g_al[2*NTOT];
__device__ __half g_Wth[512*512], g_Wtl[512*512];
__device__ float  g_logits[NTOT];

// ---------------- PTX helpers ----------------
__device__ __forceinline__ uint32_t smem_u32(const void* p) {
    uint32_t a;
    asm("{ .reg .u64 t; cvta.to.shared.u64 t, %1; cvt.u32.u64 %0, t; }" : "=r"(a) : "l"(p));
    return a;
}
__device__ __forceinline__ void cp_async16(uint32_t dst, const void* src) {
    asm volatile("cp.async.cg.shared.global [%0], [%1], 16;" :: "r"(dst), "l"(src) : "memory");
}
__device__ __forceinline__ void ldsm4(uint32_t (&r)[4], uint32_t addr) {
    asm volatile("ldmatrix.sync.aligned.m8n8.x4.shared.b16 {%0,%1,%2,%3}, [%4];"
        : "=r"(r[0]), "=r"(r[1]), "=r"(r[2]), "=r"(r[3]) : "r"(addr));
}
__device__ __forceinline__ void mma16816(float (&d)[4], const uint32_t (&a)[4],
                                         uint32_t b0, uint32_t b1) {
    asm volatile("mma.sync.aligned.m16n8k16.row.col.f32.f16.f16.f32 "
        "{%0,%1,%2,%3}, {%4,%5,%6,%7}, {%8,%9}, {%0,%1,%2,%3};"
        : "+f"(d[0]), "+f"(d[1]), "+f"(d[2]), "+f"(d[3])
        : "r"(a[0]), "r"(a[1]), "r"(a[2]), "r"(a[3]), "r"(b0), "r"(b1));
}

// ---------------------------------------------------------------------------
// fp16 split GEMM. C[M,N] = (Ah[+Al])[M,K] x (Bh[+Bl])[N,K]^T, K = 512.
// CTA tile 64x128, 256 thr, 8 warps (2m x 4n), warp tile 32x32, BK=32,
// 3-stage cp.async pipeline.
// TERMS 3: hh+lh+hl, stage 24KB, 3 CTAs/SM (85-reg cap).
// TERMS 1: hh only,  stage 12KB, 4 CTAs/SM (64-reg cap).
// MODE 0: C fp32.  MODE 1: Ch/Cl = fp16 split of tanh(C).
// ---------------------------------------------------------------------------
template<int MODE, int TERMS>
__global__ void __launch_bounds__(256, TERMS == 1 ? 4 : 3)
gemm_mma(const __half* __restrict__ Ah, const __half* __restrict__ Al,
         const __half* __restrict__ Bh, const __half* __restrict__ Bl,
         int aRows, int bRows, float* __restrict__ C, long cStride,
         __half* __restrict__ Ch, __half* __restrict__ Cl)
{
    constexpr uint32_t STG  = (TERMS == 3) ? 24576u : 12288u;  // stage bytes
    constexpr uint32_t A_LO = 4096u;                           // TERMS==3 only
    constexpr uint32_t B_HI = (TERMS == 3) ? 8192u : 4096u;
    constexpr uint32_t B_LO = 16384u;                          // TERMS==3 only

    extern __shared__ char smem[];
    const uint32_t sb = smem_u32(smem);
    const int tid = threadIdx.x, w = tid >> 5, l = tid & 31;
    const int wm = w >> 2, wn = w & 3;          // 2 m-tiles x 4 n-tiles of 32

    const size_t arow0 = (size_t)blockIdx.z * aRows + (size_t)blockIdx.y * 64;
    const size_t brow0 = (size_t)blockIdx.z * bRows + (size_t)blockIdx.x * 128;
    const char* gA_h = (const char*)(Ah + arow0 * 512);
    const char* gA_l = (const char*)(Al + arow0 * 512);
    const char* gB_h = (const char*)(Bh + brow0 * 512);
    const char* gB_l = (const char*)(Bl + brow0 * 512);

    auto load_stage = [&](int kt, int s) {
        const uint32_t sbase = sb + s * STG;
        const uint32_t kb = kt * 64;
        if (TERMS == 3) {
#pragma unroll
            for (int j = 0; j < 6; j++) {
                const int id = tid + j * 256;
                if (id < 512) {          // A: hi then lo, 256 chunks each
                    const int rem = id & 255, row = rem >> 2, c = rem & 3;
                    const char* g = (id < 256 ? gA_h : gA_l) + (size_t)row * 1024 + kb + c * 16;
                    cp_async16(sbase + (id < 256 ? 0 : A_LO) +
                               row * 64 + ((c ^ ((row >> 1) & 3)) << 4), g);
                } else {                 // B: hi then lo, 512 chunks each
                    const int bid = id - 512;
                    const int rem = bid & 511, row = rem >> 2, c = rem & 3;
                    const char* g = (bid < 512 ? gB_h : gB_l) + (size_t)row * 1024 + kb + c * 16;
                    cp_async16(sbase + (bid < 512 ? B_HI : B_LO) +
                               row * 64 + ((c ^ ((row >> 1) & 3)) << 4), g);
                }
            }
        } else {
#pragma unroll
            for (int j = 0; j < 3; j++) {
                const int id = tid + j * 256;
                if (id < 256) {          // A hi
                    const int row = id >> 2, c = id & 3;
                    const char* g = gA_h + (size_t)row * 1024 + kb + c * 16;
                    cp_async16(sbase + row * 64 + ((c ^ ((row >> 1) & 3)) << 4), g);
                } else {                 // B hi
                    const int rem = id - 256, row = rem >> 2, c = rem & 3;
                    const char* g = gB_h + (size_t)row * 1024 + kb + c * 16;
                    cp_async16(sbase + B_HI + row * 64 + ((c ^ ((row >> 1) & 3)) << 4), g);
                }
            }
        }
        asm volatile("cp.async.commit_group;" ::: "memory");
    };

    float acc[2][4][4];
#pragma unroll
    for (int i = 0; i < 2; i++)
#pragma unroll
        for (int j = 0; j < 4; j++)
#pragma unroll
            for (int k = 0; k < 4; k++) acc[i][j][k] = 0.f;

    load_stage(0, 0); load_stage(1, 1);

    for (int kt = 0; kt < 16; kt++) {
        asm volatile("cp.async.wait_group 1;" ::: "memory");
        __syncthreads();
        if (kt + 2 < 16) load_stage(kt + 2, (kt + 2) % 3);
        else asm volatile("cp.async.commit_group;" ::: "memory");

        const uint32_t st = sb + (kt % 3) * STG;
#pragma unroll
        for (int k16 = 0; k16 < 2; k16++) {
            // addressing
            const int aRow0 = wm * 32 + (l & 15);
            const int aC = k16 * 2 + (l >> 4);
            const int bRowBase = wn * 32 + ((l >> 4) << 3) + (l & 7);
            const int bC = k16 * 2 + ((l >> 3) & 1);

            uint32_t aH[2][4], bH[4][2];
            // B hi frags (4 n8-frags via 2 ldsm4)
#pragma unroll
            for (int p = 0; p < 2; p++) {
                const int row = bRowBase + p * 16;
                const uint32_t off = row * 64 + ((bC ^ ((row >> 1) & 3)) << 4);
                uint32_t t0[4];
                ldsm4(t0, st + B_HI + off);
                bH[2*p][0] = t0[0]; bH[2*p][1] = t0[1];
                bH[2*p+1][0] = t0[2]; bH[2*p+1][1] = t0[3];
            }
            // A hi frags
#pragma unroll
            for (int mt = 0; mt < 2; mt++) {
                const int row = aRow0 + mt * 16;
                const uint32_t off = row * 64 + ((aC ^ ((row >> 1) & 3)) << 4);
                ldsm4(aH[mt], st + off);
            }
            // hh
#pragma unroll
            for (int mt = 0; mt < 2; mt++)
#pragma unroll
                for (int nt = 0; nt < 4; nt++)
                    mma16816(acc[mt][nt], aH[mt], bH[nt][0], bH[nt][1]);

            if (TERMS == 3) {
                uint32_t aL[2][4];
#pragma unroll
                for (int mt = 0; mt < 2; mt++) {
                    const int row = aRow0 + mt * 16;
                    const uint32_t off = row * 64 + ((aC ^ ((row >> 1) & 3)) << 4);
                    ldsm4(aL[mt], st + A_LO + off);
                }
                // lh
#pragma unroll
                for (int mt = 0; mt < 2; mt++)
#pragma unroll
                    for (int nt = 0; nt < 4; nt++)
                        mma16816(acc[mt][nt], aL[mt], bH[nt][0], bH[nt][1]);
                // B lo frags then hl
                uint32_t bL[4][2];
#pragma unroll
                for (int p = 0; p < 2; p++) {
                    const int row = bRowBase + p * 16;
                    const uint32_t off = row * 64 + ((bC ^ ((row >> 1) & 3)) << 4);
                    uint32_t t1[4];
                    ldsm4(t1, st + B_LO + off);
                    bL[2*p][0] = t1[0]; bL[2*p][1] = t1[1];
                    bL[2*p+1][0] = t1[2]; bL[2*p+1][1] = t1[3];
                }
#pragma unroll
                for (int mt = 0; mt < 2; mt++)
#pragma unroll
                    for (int nt = 0; nt < 4; nt++)
                        mma16816(acc[mt][nt], aH[mt], bL[nt][0], bL[nt][1]);
            }
        }
    }

    // ---- epilogue: direct from registers ----
    const long cbz = (long)blockIdx.z * cStride;
#pragma unroll
    for (int mt = 0; mt < 2; mt++) {
        const int r0 = blockIdx.y * 64 + wm * 32 + mt * 16 + (l >> 2);
#pragma unroll
        for (int nt = 0; nt < 4; nt++) {
            const int col = blockIdx.x * 128 + wn * 32 + nt * 8 + ((l & 3) << 1);
            if (MODE == 0) {
                *(float2*)&C[cbz + (size_t)r0 * 512 + col]       = make_float2(acc[mt][nt][0], acc[mt][nt][1]);
                *(float2*)&C[cbz + (size_t)(r0 + 8) * 512 + col] = make_float2(acc[mt][nt][2], acc[mt][nt][3]);
            } else {
#pragma unroll
                for (int hf = 0; hf < 2; hf++) {
                    const size_t e = (size_t)(r0 + hf * 8) * 512 + col;
                    float v0 = tanhf(acc[mt][nt][hf * 2]);
                    float v1 = tanhf(acc[mt][nt][hf * 2 + 1]);
                    __half h0 = __float2half_rn(v0), h1 = __float2half_rn(v1);
                    __half l0 = __float2half_rn(v0 - __half2float(h0));
                    __half l1 = __float2half_rn(v1 - __half2float(h1));
                    *(__half2*)&Ch[e] = __halves2half2(h0, h1);
                    *(__half2*)&Cl[e] = __halves2half2(l0, l1);
                }
            }
        }
    }
}

// ---------------- split fp32 -> fp16 hi/lo, natural + per-batch transposed ----------------
__global__ void split4(const float* __restrict__ X,
                       __half* __restrict__ Xh, __half* __restrict__ Xl,
                       __half* __restrict__ Xth, __half* __restrict__ Xtl)
{
    __shared__ float tile[32][33];
    const size_t zoff = (size_t)blockIdx.z * 512 * 512;
    const int r0 = blockIdx.y * 32, c0 = blockIdx.x * 32;
    const int tx = threadIdx.x & 31, ty = threadIdx.x >> 5;
#pragma unroll
    for (int i = 0; i < 4; i++) {
        const int rr = ty + i * 8;
        const size_t e = zoff + (size_t)(r0 + rr) * 512 + c0 + tx;
        float v = X[e];
        tile[rr][tx] = v;
        __half hi = __float2half_rn(v);
        Xh[e] = hi;
        Xl[e] = __float2half_rn(v - __half2float(hi));
    }
    __syncthreads();
#pragma unroll
    for (int i = 0; i < 4; i++) {
        const int rr = ty + i * 8;
        float v = tile[tx][rr];
        const size_t e = zoff + (size_t)(c0 + rr) * 512 + r0 + tx;
        __half hi = __float2half_rn(v);
        Xth[e] = hi;
        Xtl[e] = __float2half_rn(v - __half2float(hi));
    }
}

// ---------------- per-batch transpose, hi only ----------------
__global__ void transpose_h1(const __half* __restrict__ Ah, __half* __restrict__ Th)
{
    __shared__ __half th[32][33];
    const size_t zoff = (size_t)blockIdx.z * 512 * 512;
    const int r0 = blockIdx.y * 32, c0 = blockIdx.x * 32;
    const int tx = threadIdx.x & 31, ty = threadIdx.x >> 5;
#pragma unroll
    for (int i = 0; i < 4; i++) {
        const int rr = ty + i * 8;
        th[rr][tx] = Ah[zoff + (size_t)(r0 + rr) * 512 + c0 + tx];
    }
    __syncthreads();
#pragma unroll
    for (int i = 0; i < 4; i++) {
        const int rr = ty + i * 8;
        Th[zoff + (size_t)(c0 + rr) * 512 + r0 + tx] = th[tx][rr];
    }
}

// ---------------- softmax over 512 cols, emit fp16 hi only ----------------
__global__ void softmax_h(const float* __restrict__ logits, __half* __restrict__ oh)
{
    __shared__ float red[16];
    const float* row = logits + (size_t)blockIdx.x * 512;
    const int t = threadIdx.x;
    float v0 = row[t], v1 = row[t + 256];
    float m = fmaxf(v0, v1);
#pragma unroll
    for (int o = 16; o > 0; o >>= 1) m = fmaxf(m, __shfl_xor_sync(0xffffffffu, m, o));
    if ((t & 31) == 0) red[t >> 5] = m;
    __syncthreads();
    float mA = red[0];
#pragma unroll
    for (int i = 1; i < 8; i++) mA = fmaxf(mA, red[i]);
    float e0 = expf(v0 - mA), e1 = expf(v1 - mA);
    float s = e0 + e1;
#pragma unroll
    for (int o = 16; o > 0; o >>= 1) s += __shfl_xor_sync(0xffffffffu, s, o);
    if ((t & 31) == 0) red[8 + (t >> 5)] = s;
    __syncthreads();
    float sA = 0.f;
#pragma unroll
    for (int i = 0; i < 8; i++) sA += red[8 + i];
    const float inv = 1.0f / sA;
    const size_t o0 = (size_t)blockIdx.x * 512;
    oh[o0 + t]       = __float2half_rn(e0 * inv);
    oh[o0 + t + 256] = __float2half_rn(e1 * inv);
}

// ---------------------------------------------------------------------------
extern "C" void kernel_launch(void* const* d_in, const int* in_sizes, int n_in,
                              void* d_out, int out_size)
{
    const float* P = (const float*)d_in[0];
    const float* H = (const float*)d_in[1];
    const float* W = (const float*)d_in[2];
    float* out = (float*)d_out;   // [betas ; alphas], each B*L*D fp32

    __half *Xh,*Xl,*Fh_,*Fl_,*BTh,*BTl,*ah,*al,*Wth,*Wtl;
    float* lg;
    cudaGetSymbolAddress((void**)&Xh, g_Xh);   cudaGetSymbolAddress((void**)&Xl, g_Xl);
    cudaGetSymbolAddress((void**)&Fh_, g_Fh_); cudaGetSymbolAddress((void**)&Fl_, g_Fl_);
    cudaGetSymbolAddress((void**)&BTh, g_BTh); cudaGetSymbolAddress((void**)&BTl, g_BTl);
    cudaGetSymbolAddress((void**)&ah, g_ah);   cudaGetSymbolAddress((void**)&al, g_al);
    cudaGetSymbolAddress((void**)&Wth, g_Wth); cudaGetSymbolAddress((void**)&Wtl, g_Wtl);
    cudaGetSymbolAddress((void**)&lg, g_logits);

    const int SMEM3 = 3 * 24576;   // 72 KB
    const int SMEM1 = 3 * 12288;   // 36 KB
    cudaFuncSetAttribute(gemm_mma<1,3>, cudaFuncAttributeMaxDynamicSharedMemorySize, SMEM3);
    cudaFuncSetAttribute(gemm_mma<0,3>, cudaFuncAttributeMaxDynamicSharedMemorySize, SMEM3);
    cudaFuncSetAttribute(gemm_mma<0,1>, cudaFuncAttributeMaxDynamicSharedMemorySize, SMEM1);

    dim3 b256(256);

    // 1. splits. Natural [P;H] into g_X*; transposed [Ht;Pt] into g_BT*.
    //    W natural split dumped into g_al scratch (never read), transposed kept.
    split4<<<dim3(16, 16, BB), b256>>>(P, Xh, Xl, BTh + NTOT, BTl + NTOT);
    split4<<<dim3(16, 16, BB), b256>>>(H, Xh + NTOT, Xl + NTOT, BTh, BTl);
    split4<<<dim3(16, 16, 1),  b256>>>(W, al, al + NTOT, Wth, Wtl);

    // 2. merged projection: [Fp;Fh] = tanh([P;H] @ W), M = 65536, 3-term
    gemm_mma<1,3><<<dim3(4, 1024, 1), b256, SMEM3>>>(Xh, Xl, Wth, Wtl, 0, 0,
                                                     nullptr, 0, Fh_, Fl_);

    // 3. logits = F_p @ F_h^T per batch, 3-term
    gemm_mma<0,3><<<dim3(4, 8, BB), b256, SMEM3>>>(Fh_, Fl_, Fh_ + NTOT, Fl_ + NTOT,
                                                   512, 512, lg, (long)512 * 512,
                                                   nullptr, nullptr);

    // 4. softmax -> attn hi; transpose -> attn^T hi
    softmax_h<<<BB * LL, b256>>>(lg, ah);
    transpose_h1<<<dim3(16, 16, BB), b256>>>(ah, ah + NTOT);

    // 5. merged output GEMM, 1-term (hi x hi), z in [0,128):
    //    z<64 : betas  = attn   @ Ht-rows -> out[z]
    //    z>=64: alphas = attn^T @ Pt-rows -> out[z]
    gemm_mma<0,1><<<dim3(4, 8, 2 * BB), b256, SMEM1>>>(ah, ah, BTh, BTh, 512, 512,
                                                       out, (long)512 * 512,
                                                       nullptr, nullptr);
}

// round 16
// speedup vs baseline: 1.1454x; 1.1454x over previous
#include <cuda_runtime.h>
#include <cuda_fp16.h>
#include <math.h>
#include <stdint.h>

#define BB 64
#define LL 512
#define DD 512

// stage = A(128x32 hi+lo) 16KB + B(128x32 hi+lo) 16KB = 32KB; 3 stages
#define STG_BYTES 32768
#define SMEM_DYN (3 * STG_BYTES)

// ---------------- scratch (no cudaMalloc allowed) ----------------
//  g_X*  : [P ; H] natural K-major splits (proj A operand, hi+lo)
//  g_F*  : [Fp ; Fh] (logits operands, hi+lo)
//  g_BTh : [H^T-rows ; P^T-rows] (out-GEMM B operand, hi only)
//  g_ah  : [attn ; attn^T] (hi only)
#define NTOT (32768ull * 512ull)
__device__ __half g_Xh[2*NTOT], g_Xl[2*NTOT];
__device__ __half g_Fh_[2*NTOT], g_Fl_[2*NTOT];
__device__ __half g_BTh[2*NTOT];
__device__ __half g_ah[2*NTOT];
__device__ __half g_Wth[512*512], g_Wtl[512*512];
__device__ float  g_logits[NTOT];

// ---------------- PTX helpers ----------------
__device__ __forceinline__ uint32_t smem_u32(const void* p) {
    uint32_t a;
    asm("{ .reg .u64 t; cvta.to.shared.u64 t, %1; cvt.u32.u64 %0, t; }" : "=r"(a) : "l"(p));
    return a;
}
__device__ __forceinline__ void cp_async16(uint32_t dst, const void* src) {
    asm volatile("cp.async.cg.shared.global [%0], [%1], 16;" :: "r"(dst), "l"(src) : "memory");
}
__device__ __forceinline__ void ldsm4(uint32_t (&r)[4], uint32_t addr) {
    asm volatile("ldmatrix.sync.aligned.m8n8.x4.shared.b16 {%0,%1,%2,%3}, [%4];"
        : "=r"(r[0]), "=r"(r[1]), "=r"(r[2]), "=r"(r[3]) : "r"(addr));
}
__device__ __forceinline__ void mma16816(float (&d)[4], const uint32_t (&a)[4],
                                         uint32_t b0, uint32_t b1) {
    asm volatile("mma.sync.aligned.m16n8k16.row.col.f32.f16.f16.f32 "
        "{%0,%1,%2,%3}, {%4,%5,%6,%7}, {%8,%9}, {%0,%1,%2,%3};"
        : "+f"(d[0]), "+f"(d[1]), "+f"(d[2]), "+f"(d[3])
        : "r"(a[0]), "r"(a[1]), "r"(a[2]), "r"(a[3]), "r"(b0), "r"(b1));
}

// ---------------------------------------------------------------------------
// fp16 split GEMM. C[M,N] = (Ah[+Al])[M,K] x (Bh[+Bl])[N,K]^T, K = 512.
// CTA tile 128x128, 256 thr, 8 warps (2m x 4n), warp tile 64x32, BK=32,
// 3-stage cp.async pipeline, 2 CTAs/SM (128-reg cap).
// TERMS 3: hh+lh+hl.  TERMS 1: hh only (A-lo/B-lo never loaded).
// MODE 0: C fp32.  MODE 1: Ch/Cl = fp16 split of tanh(C).
// ---------------------------------------------------------------------------
template<int MODE, int TERMS>
__global__ void __launch_bounds__(256, 2)
gemm_mma(const __half* __restrict__ Ah, const __half* __restrict__ Al,
         const __half* __restrict__ Bh, const __half* __restrict__ Bl,
         int aRows, int bRows, float* __restrict__ C, long cStride,
         __half* __restrict__ Ch, __half* __restrict__ Cl)
{
    extern __shared__ char smem[];
    const uint32_t sb = smem_u32(smem);
    const int tid = threadIdx.x, w = tid >> 5, l = tid & 31;
    const int wm = w >> 2, wn = w & 3;

    const size_t arow0 = (size_t)blockIdx.z * aRows + (size_t)blockIdx.y * 128;
    const size_t brow0 = (size_t)blockIdx.z * bRows + (size_t)blockIdx.x * 128;
    const char* gsrc[4] = {
        (const char*)(Ah + arow0 * 512), (const char*)(Al + arow0 * 512),
        (const char*)(Bh + brow0 * 512), (const char*)(Bl + brow0 * 512) };

    // stage layout: Ah[0,8K) Al[8K,16K) Bh[16K,24K) Bl[24K,32K)
    auto load_stage = [&](int kt, int s) {
        const uint32_t sbase = sb + s * STG_BYTES;
#pragma unroll
        for (int j = 0; j < 8; j++) {
            const int id = tid + j * 256;
            const int arr = id >> 9;                 // 0=Ah 1=Al 2=Bh 3=Bl
            if (TERMS == 1 && (arr == 1 || arr == 3)) continue;
            const int rem = id & 511, row = rem >> 2, c = rem & 3;
            const char* g = gsrc[arr] + (size_t)row * 1024 + kt * 64 + c * 16;
            cp_async16(sbase + arr * 8192 + row * 64 + ((c ^ ((row >> 1) & 3)) << 4), g);
        }
        asm volatile("cp.async.commit_group;" ::: "memory");
    };

    float acc[4][4][4];
#pragma unroll
    for (int i = 0; i < 4; i++)
#pragma unroll
        for (int j = 0; j < 4; j++)
#pragma unroll
            for (int k = 0; k < 4; k++) acc[i][j][k] = 0.f;

    load_stage(0, 0); load_stage(1, 1);

    for (int kt = 0; kt < 16; kt++) {
        asm volatile("cp.async.wait_group 1;" ::: "memory");
        __syncthreads();
        if (kt + 2 < 16) load_stage(kt + 2, (kt + 2) % 3);
        else asm volatile("cp.async.commit_group;" ::: "memory");

        const uint32_t st = sb + (kt % 3) * STG_BYTES;
#pragma unroll
        for (int k16 = 0; k16 < 2; k16++) {
            uint32_t bH[4][2], bL[4][2], aH[4][4], aL[4][4];
            // ---- hoisted fragment loads ----
#pragma unroll
            for (int p = 0; p < 2; p++) {
                const int row = wn * 32 + p * 16 + ((l >> 4) << 3) + (l & 7);
                const int c = k16 * 2 + ((l >> 3) & 1);
                const uint32_t off = row * 64 + ((c ^ ((row >> 1) & 3)) << 4);
                uint32_t t0[4];
                ldsm4(t0, st + 16384 + off);
                bH[2*p][0] = t0[0]; bH[2*p][1] = t0[1];
                bH[2*p+1][0] = t0[2]; bH[2*p+1][1] = t0[3];
                if (TERMS == 3) {
                    uint32_t t1[4];
                    ldsm4(t1, st + 24576 + off);
                    bL[2*p][0] = t1[0]; bL[2*p][1] = t1[1];
                    bL[2*p+1][0] = t1[2]; bL[2*p+1][1] = t1[3];
                }
            }
#pragma unroll
            for (int mt = 0; mt < 4; mt++) {
                const int row = wm * 64 + mt * 16 + (l & 15);
                const int c = k16 * 2 + (l >> 4);
                const uint32_t off = row * 64 + ((c ^ ((row >> 1) & 3)) << 4);
                ldsm4(aH[mt], st + off);
                if (TERMS == 3) ldsm4(aL[mt], st + 8192 + off);
            }
            // ---- MMAs, term-major ----
#pragma unroll
            for (int mt = 0; mt < 4; mt++)
#pragma unroll
                for (int nt = 0; nt < 4; nt++)
                    mma16816(acc[mt][nt], aH[mt], bH[nt][0], bH[nt][1]);
            if (TERMS == 3) {
#pragma unroll
                for (int mt = 0; mt < 4; mt++)
#pragma unroll
                    for (int nt = 0; nt < 4; nt++)
                        mma16816(acc[mt][nt], aL[mt], bH[nt][0], bH[nt][1]);
#pragma unroll
                for (int mt = 0; mt < 4; mt++)
#pragma unroll
                    for (int nt = 0; nt < 4; nt++)
                        mma16816(acc[mt][nt], aH[mt], bL[nt][0], bL[nt][1]);
            }
        }
    }

    // ---- epilogue: direct from registers ----
    const long cbz = (long)blockIdx.z * cStride;
#pragma unroll
    for (int mt = 0; mt < 4; mt++) {
        const int r0 = blockIdx.y * 128 + wm * 64 + mt * 16 + (l >> 2);
#pragma unroll
        for (int nt = 0; nt < 4; nt++) {
            const int col = blockIdx.x * 128 + wn * 32 + nt * 8 + ((l & 3) << 1);
            if (MODE == 0) {
                *(float2*)&C[cbz + (size_t)r0 * 512 + col]       = make_float2(acc[mt][nt][0], acc[mt][nt][1]);
                *(float2*)&C[cbz + (size_t)(r0 + 8) * 512 + col] = make_float2(acc[mt][nt][2], acc[mt][nt][3]);
            } else {
#pragma unroll
                for (int hf = 0; hf < 2; hf++) {
                    const size_t e = (size_t)(r0 + hf * 8) * 512 + col;
                    float v0 = tanhf(acc[mt][nt][hf * 2]);
                    float v1 = tanhf(acc[mt][nt][hf * 2 + 1]);
                    __half h0 = __float2half_rn(v0), h1 = __float2half_rn(v1);
                    __half l0 = __float2half_rn(v0 - __half2float(h0));
                    __half l1 = __float2half_rn(v1 - __half2float(h1));
                    *(__half2*)&Ch[e] = __halves2half2(h0, h1);
                    *(__half2*)&Cl[e] = __halves2half2(l0, l1);
                }
            }
        }
    }
}

// ---- split fp32 -> natural hi/lo + transposed hi only (lo-transposed dead) ----
__global__ void split3(const float* __restrict__ X,
                       __half* __restrict__ Xh, __half* __restrict__ Xl,
                       __half* __restrict__ Xth)
{
    __shared__ float tile[32][33];
    const size_t zoff = (size_t)blockIdx.z * 512 * 512;
    const int r0 = blockIdx.y * 32, c0 = blockIdx.x * 32;
    const int tx = threadIdx.x & 31, ty = threadIdx.x >> 5;
#pragma unroll
    for (int i = 0; i < 4; i++) {
        const int rr = ty + i * 8;
        const size_t e = zoff + (size_t)(r0 + rr) * 512 + c0 + tx;
        float v = X[e];
        tile[rr][tx] = v;
        __half hi = __float2half_rn(v);
        Xh[e] = hi;
        Xl[e] = __float2half_rn(v - __half2float(hi));
    }
    __syncthreads();
#pragma unroll
    for (int i = 0; i < 4; i++) {
        const int rr = ty + i * 8;
        Xth[zoff + (size_t)(c0 + rr) * 512 + r0 + tx] = __float2half_rn(tile[tx][rr]);
    }
}

// ---- W split: transposed hi/lo only (natural never used) ----
__global__ void splitT(const float* __restrict__ X,
                       __half* __restrict__ Xth, __half* __restrict__ Xtl)
{
    __shared__ float tile[32][33];
    const int r0 = blockIdx.y * 32, c0 = blockIdx.x * 32;
    const int tx = threadIdx.x & 31, ty = threadIdx.x >> 5;
#pragma unroll
    for (int i = 0; i < 4; i++) {
        const int rr = ty + i * 8;
        tile[rr][tx] = X[(size_t)(r0 + rr) * 512 + c0 + tx];
    }
    __syncthreads();
#pragma unroll
    for (int i = 0; i < 4; i++) {
        const int rr = ty + i * 8;
        float v = tile[tx][rr];
        const size_t e = (size_t)(c0 + rr) * 512 + r0 + tx;
        __half hi = __float2half_rn(v);
        Xth[e] = hi;
        Xtl[e] = __float2half_rn(v - __half2float(hi));
    }
}

// ---------------- per-batch transpose, hi only ----------------
__global__ void transpose_h1(const __half* __restrict__ Ah, __half* __restrict__ Th)
{
    __shared__ __half th[32][33];
    const size_t zoff = (size_t)blockIdx.z * 512 * 512;
    const int r0 = blockIdx.y * 32, c0 = blockIdx.x * 32;
    const int tx = threadIdx.x & 31, ty = threadIdx.x >> 5;
#pragma unroll
    for (int i = 0; i < 4; i++) {
        const int rr = ty + i * 8;
        th[rr][tx] = Ah[zoff + (size_t)(r0 + rr) * 512 + c0 + tx];
    }
    __syncthreads();
#pragma unroll
    for (int i = 0; i < 4; i++) {
        const int rr = ty + i * 8;
        Th[zoff + (size_t)(c0 + rr) * 512 + r0 + tx] = th[tx][rr];
    }
}

// ---------------- softmax over 512 cols, emit fp16 hi only ----------------
__global__ void softmax_h(const float* __restrict__ logits, __half* __restrict__ oh)
{
    __shared__ float red[16];
    const float* row = logits + (size_t)blockIdx.x * 512;
    const int t = threadIdx.x;
    float v0 = row[t], v1 = row[t + 256];
    float m = fmaxf(v0, v1);
#pragma unroll
    for (int o = 16; o > 0; o >>= 1) m = fmaxf(m, __shfl_xor_sync(0xffffffffu, m, o));
    if ((t & 31) == 0) red[t >> 5] = m;
    __syncthreads();
    float mA = red[0];
#pragma unroll
    for (int i = 1; i < 8; i++) mA = fmaxf(mA, red[i]);
    float e0 = expf(v0 - mA), e1 = expf(v1 - mA);
    float s = e0 + e1;
#pragma unroll
    for (int o = 16; o > 0; o >>= 1) s += __shfl_xor_sync(0xffffffffu, s, o);
    if ((t & 31) == 0) red[8 + (t >> 5)] = s;
    __syncthreads();
    float sA = 0.f;
#pragma unroll
    for (int i = 0; i < 8; i++) sA += red[8 + i];
    const float inv = 1.0f / sA;
    const size_t o0 = (size_t)blockIdx.x * 512;
    oh[o0 + t]       = __float2half_rn(e0 * inv);
    oh[o0 + t + 256] = __float2half_rn(e1 * inv);
}

// ---------------------------------------------------------------------------
extern "C" void kernel_launch(void* const* d_in, const int* in_sizes, int n_in,
                              void* d_out, int out_size)
{
    const float* P = (const float*)d_in[0];
    const float* H = (const float*)d_in[1];
    const float* W = (const float*)d_in[2];
    float* out = (float*)d_out;   // [betas ; alphas], each B*L*D fp32

    __half *Xh,*Xl,*Fh_,*Fl_,*BTh,*ah,*Wth,*Wtl;
    float* lg;
    cudaGetSymbolAddress((void**)&Xh, g_Xh);   cudaGetSymbolAddress((void**)&Xl, g_Xl);
    cudaGetSymbolAddress((void**)&Fh_, g_Fh_); cudaGetSymbolAddress((void**)&Fl_, g_Fl_);
    cudaGetSymbolAddress((void**)&BTh, g_BTh); cudaGetSymbolAddress((void**)&ah, g_ah);
    cudaGetSymbolAddress((void**)&Wth, g_Wth); cudaGetSymbolAddress((void**)&Wtl, g_Wtl);
    cudaGetSymbolAddress((void**)&lg, g_logits);

    cudaFuncSetAttribute(gemm_mma<1,3>, cudaFuncAttributeMaxDynamicSharedMemorySize, SMEM_DYN);
    cudaFuncSetAttribute(gemm_mma<0,3>, cudaFuncAttributeMaxDynamicSharedMemorySize, SMEM_DYN);
    cudaFuncSetAttribute(gemm_mma<0,1>, cudaFuncAttributeMaxDynamicSharedMemorySize, SMEM_DYN);

    dim3 b256(256);

    // 1. splits. Natural [P;H] -> g_X* (hi+lo); transposed hi only -> g_BTh
    //    as [Ht ; Pt] (Ht first: betas B operand). W -> transposed hi/lo.
    split3<<<dim3(16, 16, BB), b256>>>(P, Xh, Xl, BTh + NTOT);
    split3<<<dim3(16, 16, BB), b256>>>(H, Xh + NTOT, Xl + NTOT, BTh);
    splitT<<<dim3(16, 16, 1),  b256>>>(W, Wth, Wtl);

    // 2. merged projection: [Fp;Fh] = tanh([P;H] @ W), M = 65536, 3-term
    gemm_mma<1,3><<<dim3(4, 512, 1), b256, SMEM_DYN>>>(Xh, Xl, Wth, Wtl, 0, 0,
                                                       nullptr, 0, Fh_, Fl_);

    // 3. logits = F_p @ F_h^T per batch, 3-term
    gemm_mma<0,3><<<dim3(4, 4, BB), b256, SMEM_DYN>>>(Fh_, Fl_, Fh_ + NTOT, Fl_ + NTOT,
                                                      512, 512, lg, (long)512 * 512,
                                                      nullptr, nullptr);

    // 4. softmax -> attn hi; transpose -> attn^T hi
    softmax_h<<<BB * LL, b256>>>(lg, ah);
    transpose_h1<<<dim3(16, 16, BB), b256>>>(ah, ah + NTOT);

    // 5. merged output GEMM, 1-term (hi x hi), z in [0,128):
    //    z<64 : betas  = attn   @ Ht-rows -> out[z]
    //    z>=64: alphas = attn^T @ Pt-rows -> out[z]
    gemm_mma<0,1><<<dim3(4, 4, 2 * BB), b256, SMEM_DYN>>>(ah, ah, BTh, BTh, 512, 512,
                                                          out, (long)512 * 512,
                                                          nullptr, nullptr);
}

// round 17
// speedup vs baseline: 1.1871x; 1.0365x over previous
#include <cuda_runtime.h>
#include <cuda_fp16.h>
#include <math.h>
#include <stdint.h>

#define BB 64
#define LL 512
#define DD 512

// proj/logits stage = A(128x32 hi+lo) 16KB + B(128x32 hi+lo) 16KB = 32KB; 3 stages
#define STG_BYTES 32768
#define SMEM_DYN (3 * STG_BYTES)
// out-GEMM stage = A 8KB + B 8KB = 16KB; 3 stages
#define OSTG 16384
#define OSMEM (3 * OSTG)

// ---------------- scratch (no cudaMalloc allowed) ----------------
#define NTOT (32768ull * 512ull)
__device__ __half g_Xh[2*NTOT], g_Xl[2*NTOT];     // [P;H] natural hi/lo
__device__ __half g_Fh_[2*NTOT], g_Fl_[2*NTOT];   // [Fp;Fh] hi/lo
__device__ __half g_ah[NTOT];                     // attn hi (natural only)
__device__ __half g_Wth[512*512], g_Wtl[512*512]; // W^T rows hi/lo
__device__ float  g_logits[NTOT];

// ---------------- PTX helpers ----------------
__device__ __forceinline__ uint32_t smem_u32(const void* p) {
    uint32_t a;
    asm("{ .reg .u64 t; cvta.to.shared.u64 t, %1; cvt.u32.u64 %0, t; }" : "=r"(a) : "l"(p));
    return a;
}
__device__ __forceinline__ void cp_async16(uint32_t dst, const void* src) {
    asm volatile("cp.async.cg.shared.global [%0], [%1], 16;" :: "r"(dst), "l"(src) : "memory");
}
__device__ __forceinline__ void ldsm4(uint32_t (&r)[4], uint32_t addr) {
    asm volatile("ldmatrix.sync.aligned.m8n8.x4.shared.b16 {%0,%1,%2,%3}, [%4];"
        : "=r"(r[0]), "=r"(r[1]), "=r"(r[2]), "=r"(r[3]) : "r"(addr));
}
__device__ __forceinline__ void ldsm4t(uint32_t (&r)[4], uint32_t addr) {
    asm volatile("ldmatrix.sync.aligned.m8n8.x4.trans.shared.b16 {%0,%1,%2,%3}, [%4];"
        : "=r"(r[0]), "=r"(r[1]), "=r"(r[2]), "=r"(r[3]) : "r"(addr));
}
__device__ __forceinline__ void mma16816(float (&d)[4], const uint32_t (&a)[4],
                                         uint32_t b0, uint32_t b1) {
    asm volatile("mma.sync.aligned.m16n8k16.row.col.f32.f16.f16.f32 "
        "{%0,%1,%2,%3}, {%4,%5,%6,%7}, {%8,%9}, {%0,%1,%2,%3};"
        : "+f"(d[0]), "+f"(d[1]), "+f"(d[2]), "+f"(d[3])
        : "r"(a[0]), "r"(a[1]), "r"(a[2]), "r"(a[3]), "r"(b0), "r"(b1));
}

// ---------------------------------------------------------------------------
// 3-term fp16 split GEMM (proj + logits). C = (Ah+Al)(Bh+Bl)^T, both K-major.
// CTA 128x128, 256 thr, warp tile 64x32, BK=32, 3-stage, 2 CTAs/SM.
// MODE 0: C fp32.  MODE 1: Ch/Cl = fp16 split of tanh(C).
// ---------------------------------------------------------------------------
template<int MODE>
__global__ void __launch_bounds__(256, 2)
gemm_mma(const __half* __restrict__ Ah, const __half* __restrict__ Al,
         const __half* __restrict__ Bh, const __half* __restrict__ Bl,
         int aRows, int bRows, float* __restrict__ C, long cStride,
         __half* __restrict__ Ch, __half* __restrict__ Cl)
{
    extern __shared__ char smem[];
    const uint32_t sb = smem_u32(smem);
    const int tid = threadIdx.x, w = tid >> 5, l = tid & 31;
    const int wm = w >> 2, wn = w & 3;

    const size_t arow0 = (size_t)blockIdx.z * aRows + (size_t)blockIdx.y * 128;
    const size_t brow0 = (size_t)blockIdx.z * bRows + (size_t)blockIdx.x * 128;
    const char* gsrc[4] = {
        (const char*)(Ah + arow0 * 512), (const char*)(Al + arow0 * 512),
        (const char*)(Bh + brow0 * 512), (const char*)(Bl + brow0 * 512) };

    auto load_stage = [&](int kt, int s) {
        const uint32_t sbase = sb + s * STG_BYTES;
#pragma unroll
        for (int j = 0; j < 8; j++) {
            const int id = tid + j * 256;
            const int arr = id >> 9;
            const int rem = id & 511, row = rem >> 2, c = rem & 3;
            const char* g = gsrc[arr] + (size_t)row * 1024 + kt * 64 + c * 16;
            cp_async16(sbase + arr * 8192 + row * 64 + ((c ^ ((row >> 1) & 3)) << 4), g);
        }
        asm volatile("cp.async.commit_group;" ::: "memory");
    };

    float acc[4][4][4];
#pragma unroll
    for (int i = 0; i < 4; i++)
#pragma unroll
        for (int j = 0; j < 4; j++)
#pragma unroll
            for (int k = 0; k < 4; k++) acc[i][j][k] = 0.f;

    load_stage(0, 0); load_stage(1, 1);

    for (int kt = 0; kt < 16; kt++) {
        asm volatile("cp.async.wait_group 1;" ::: "memory");
        __syncthreads();
        if (kt + 2 < 16) load_stage(kt + 2, (kt + 2) % 3);
        else asm volatile("cp.async.commit_group;" ::: "memory");

        const uint32_t st = sb + (kt % 3) * STG_BYTES;
#pragma unroll
        for (int k16 = 0; k16 < 2; k16++) {
            uint32_t bH[4][2], bL[4][2], aH[4][4], aL[4][4];
#pragma unroll
            for (int p = 0; p < 2; p++) {
                const int row = wn * 32 + p * 16 + ((l >> 4) << 3) + (l & 7);
                const int c = k16 * 2 + ((l >> 3) & 1);
                const uint32_t off = row * 64 + ((c ^ ((row >> 1) & 3)) << 4);
                uint32_t t0[4], t1[4];
                ldsm4(t0, st + 16384 + off);
                ldsm4(t1, st + 24576 + off);
                bH[2*p][0] = t0[0]; bH[2*p][1] = t0[1];
                bH[2*p+1][0] = t0[2]; bH[2*p+1][1] = t0[3];
                bL[2*p][0] = t1[0]; bL[2*p][1] = t1[1];
                bL[2*p+1][0] = t1[2]; bL[2*p+1][1] = t1[3];
            }
#pragma unroll
            for (int mt = 0; mt < 4; mt++) {
                const int row = wm * 64 + mt * 16 + (l & 15);
                const int c = k16 * 2 + (l >> 4);
                const uint32_t off = row * 64 + ((c ^ ((row >> 1) & 3)) << 4);
                ldsm4(aH[mt], st + off);
                ldsm4(aL[mt], st + 8192 + off);
            }
#pragma unroll
            for (int mt = 0; mt < 4; mt++)
#pragma unroll
                for (int nt = 0; nt < 4; nt++)
                    mma16816(acc[mt][nt], aH[mt], bH[nt][0], bH[nt][1]);
#pragma unroll
            for (int mt = 0; mt < 4; mt++)
#pragma unroll
                for (int nt = 0; nt < 4; nt++)
                    mma16816(acc[mt][nt], aL[mt], bH[nt][0], bH[nt][1]);
#pragma unroll
            for (int mt = 0; mt < 4; mt++)
#pragma unroll
                for (int nt = 0; nt < 4; nt++)
                    mma16816(acc[mt][nt], aH[mt], bL[nt][0], bL[nt][1]);
        }
    }

    const long cbz = (long)blockIdx.z * cStride;
#pragma unroll
    for (int mt = 0; mt < 4; mt++) {
        const int r0 = blockIdx.y * 128 + wm * 64 + mt * 16 + (l >> 2);
#pragma unroll
        for (int nt = 0; nt < 4; nt++) {
            const int col = blockIdx.x * 128 + wn * 32 + nt * 8 + ((l & 3) << 1);
            if (MODE == 0) {
                *(float2*)&C[cbz + (size_t)r0 * 512 + col]       = make_float2(acc[mt][nt][0], acc[mt][nt][1]);
                *(float2*)&C[cbz + (size_t)(r0 + 8) * 512 + col] = make_float2(acc[mt][nt][2], acc[mt][nt][3]);
            } else {
#pragma unroll
                for (int hf = 0; hf < 2; hf++) {
                    const size_t e = (size_t)(r0 + hf * 8) * 512 + col;
                    float v0 = tanhf(acc[mt][nt][hf * 2]);
                    float v1 = tanhf(acc[mt][nt][hf * 2 + 1]);
                    __half h0 = __float2half_rn(v0), h1 = __float2half_rn(v1);
                    __half l0 = __float2half_rn(v0 - __half2float(h0));
                    __half l1 = __float2half_rn(v1 - __half2float(h1));
                    *(__half2*)&Ch[e] = __halves2half2(h0, h1);
                    *(__half2*)&Cl[e] = __halves2half2(l0, l1);
                }
            }
        }
    }
}

// ---------------------------------------------------------------------------
// 1-term output GEMM with trans-fragment loads (no transposed copies needed).
// C[M,N] = A x B, K = 512, batch z (stride 512*512 on all three).
// AT=0 (betas):  A = attn K-major [m,k];      B = H natural [k][n] (trans-load)
// AT=1 (alphas): A = attn M-major (trans),    B = P natural [k][n] (trans-load)
// CTA 128x128, warp 64x32, BK=32, 3-stage x 16KB.
// Trans tile layout: [k:32][n:128] halfs, row 256B, chunk swizzle nc ^= (k&7).
// ---------------------------------------------------------------------------
template<int AT>
__global__ void __launch_bounds__(256, 2)
gemm_out(const __half* __restrict__ A, const __half* __restrict__ B,
         float* __restrict__ C)
{
    extern __shared__ char smem[];
    const uint32_t sb = smem_u32(smem);
    const int tid = threadIdx.x, w = tid >> 5, l = tid & 31;
    const int wm = w >> 2, wn = w & 3;

    const char* gA = (const char*)(A + (size_t)blockIdx.z * 262144);
    const char* gB = (const char*)(B + (size_t)blockIdx.z * 262144);

    auto load_stage = [&](int kt, int s) {
        const uint32_t sbase = sb + s * OSTG;
#pragma unroll
        for (int j = 0; j < 4; j++) {
            const int id = tid + j * 256;
            if (id < 512) {          // A region
                if (AT == 0) {
                    const int row = id >> 2, c = id & 3;
                    const char* g = gA + (blockIdx.y * 128 + row) * 1024 + kt * 64 + c * 16;
                    cp_async16(sbase + row * 64 + ((c ^ ((row >> 1) & 3)) << 4), g);
                } else {
                    const int k = id >> 4, nc = id & 15;
                    const char* g = gA + (size_t)(kt * 32 + k) * 1024 + blockIdx.y * 256 + nc * 16;
                    cp_async16(sbase + k * 256 + ((nc ^ (k & 7)) << 4), g);
                }
            } else {                 // B region (always trans tile)
                const int bid = id - 512, k = bid >> 4, nc = bid & 15;
                const char* g = gB + (size_t)(kt * 32 + k) * 1024 + blockIdx.x * 256 + nc * 16;
                cp_async16(sbase + 8192 + k * 256 + ((nc ^ (k & 7)) << 4), g);
            }
        }
        asm volatile("cp.async.commit_group;" ::: "memory");
    };

    float acc[4][4][4];
#pragma unroll
    for (int i = 0; i < 4; i++)
#pragma unroll
        for (int j = 0; j < 4; j++)
#pragma unroll
            for (int k = 0; k < 4; k++) acc[i][j][k] = 0.f;

    load_stage(0, 0); load_stage(1, 1);

    for (int kt = 0; kt < 16; kt++) {
        asm volatile("cp.async.wait_group 1;" ::: "memory");
        __syncthreads();
        if (kt + 2 < 16) load_stage(kt + 2, (kt + 2) % 3);
        else asm volatile("cp.async.commit_group;" ::: "memory");

        const uint32_t st = sb + (kt % 3) * OSTG;
#pragma unroll
        for (int k16 = 0; k16 < 2; k16++) {
            uint32_t bH[4][2], aH[4][4];
            // B frags via ldsm.trans: m0=(k0-7,n0-7) m1=(k8-15,n0-7) m2/m3 = n8-15
#pragma unroll
            for (int p = 0; p < 2; p++) {
                const int krow = k16 * 16 + ((l >> 3) & 1) * 8 + (l & 7);
                const int nc = wn * 4 + p * 2 + ((l >> 4) & 1);
                const uint32_t off = krow * 256 + ((nc ^ (krow & 7)) << 4);
                uint32_t t[4];
                ldsm4t(t, st + 8192 + off);
                bH[2*p][0] = t[0]; bH[2*p][1] = t[1];
                bH[2*p+1][0] = t[2]; bH[2*p+1][1] = t[3];
            }
            // A frags
#pragma unroll
            for (int mt = 0; mt < 4; mt++) {
                if (AT == 0) {
                    const int row = wm * 64 + mt * 16 + (l & 15);
                    const int c = k16 * 2 + (l >> 4);
                    const uint32_t off = row * 64 + ((c ^ ((row >> 1) & 3)) << 4);
                    ldsm4(aH[mt], st + off);
                } else {
                    // a0=(m0-7,k0-7) a1=(m8-15,k0-7) a2=(m0-7,k8-15) a3=(m8-15,k8-15)
                    const int krow = k16 * 16 + ((l >> 4) << 3) + (l & 7);
                    const int mc = wm * 8 + mt * 2 + ((l >> 3) & 1);
                    const uint32_t off = krow * 256 + ((mc ^ (krow & 7)) << 4);
                    ldsm4t(aH[mt], st + off);
                }
            }
#pragma unroll
            for (int mt = 0; mt < 4; mt++)
#pragma unroll
                for (int nt = 0; nt < 4; nt++)
                    mma16816(acc[mt][nt], aH[mt], bH[nt][0], bH[nt][1]);
        }
    }

    const size_t cbz = (size_t)blockIdx.z * 262144;
#pragma unroll
    for (int mt = 0; mt < 4; mt++) {
        const int r0 = blockIdx.y * 128 + wm * 64 + mt * 16 + (l >> 2);
#pragma unroll
        for (int nt = 0; nt < 4; nt++) {
            const int col = blockIdx.x * 128 + wn * 32 + nt * 8 + ((l & 3) << 1);
            *(float2*)&C[cbz + (size_t)r0 * 512 + col]       = make_float2(acc[mt][nt][0], acc[mt][nt][1]);
            *(float2*)&C[cbz + (size_t)(r0 + 8) * 512 + col] = make_float2(acc[mt][nt][2], acc[mt][nt][3]);
        }
    }
}

// ---- streaming split: fp32 -> fp16 hi/lo (natural layout only), [P;H] merged ----
__global__ void split2(const float* __restrict__ P, const float* __restrict__ Hsrc,
                       __half* __restrict__ Xh, __half* __restrict__ Xl)
{
    const size_t e = ((size_t)blockIdx.x * 256 + threadIdx.x) * 4;
    const float* src = (e < NTOT) ? (P + e) : (Hsrc + (e - NTOT));
    float4 v = *(const float4*)src;
    __half h0 = __float2half_rn(v.x), h1 = __float2half_rn(v.y);
    __half h2 = __float2half_rn(v.z), h3 = __float2half_rn(v.w);
    __half l0 = __float2half_rn(v.x - __half2float(h0));
    __half l1 = __float2half_rn(v.y - __half2float(h1));
    __half l2 = __float2half_rn(v.z - __half2float(h2));
    __half l3 = __float2half_rn(v.w - __half2float(h3));
    __half2 hv[2] = { __halves2half2(h0, h1), __halves2half2(h2, h3) };
    __half2 lv[2] = { __halves2half2(l0, l1), __halves2half2(l2, l3) };
    *(uint2*)(Xh + e) = *(uint2*)hv;
    *(uint2*)(Xl + e) = *(uint2*)lv;
}

// ---- W split: transposed hi/lo (W^T rows, K-major for proj B) ----
__global__ void splitT(const float* __restrict__ X,
                       __half* __restrict__ Xth, __half* __restrict__ Xtl)
{
    __shared__ float tile[32][33];
    const int r0 = blockIdx.y * 32, c0 = blockIdx.x * 32;
    const int tx = threadIdx.x & 31, ty = threadIdx.x >> 5;
#pragma unroll
    for (int i = 0; i < 4; i++) {
        const int rr = ty + i * 8;
        tile[rr][tx] = X[(size_t)(r0 + rr) * 512 + c0 + tx];
    }
    __syncthreads();
#pragma unroll
    for (int i = 0; i < 4; i++) {
        const int rr = ty + i * 8;
        float v = tile[tx][rr];
        const size_t e = (size_t)(c0 + rr) * 512 + r0 + tx;
        __half hi = __float2half_rn(v);
        Xth[e] = hi;
        Xtl[e] = __float2half_rn(v - __half2float(hi));
    }
}

// ---------------- softmax over 512 cols, emit fp16 hi only ----------------
__global__ void softmax_h(const float* __restrict__ logits, __half* __restrict__ oh)
{
    __shared__ float red[16];
    const float* row = logits + (size_t)blockIdx.x * 512;
    const int t = threadIdx.x;
    float v0 = row[t], v1 = row[t + 256];
    float m = fmaxf(v0, v1);
#pragma unroll
    for (int o = 16; o > 0; o >>= 1) m = fmaxf(m, __shfl_xor_sync(0xffffffffu, m, o));
    if ((t & 31) == 0) red[t >> 5] = m;
    __syncthreads();
    float mA = red[0];
#pragma unroll
    for (int i = 1; i < 8; i++) mA = fmaxf(mA, red[i]);
    float e0 = expf(v0 - mA), e1 = expf(v1 - mA);
    float s = e0 + e1;
#pragma unroll
    for (int o = 16; o > 0; o >>= 1) s += __shfl_xor_sync(0xffffffffu, s, o);
    if ((t & 31) == 0) red[8 + (t >> 5)] = s;
    __syncthreads();
    float sA = 0.f;
#pragma unroll
    for (int i = 0; i < 8; i++) sA += red[8 + i];
    const float inv = 1.0f / sA;
    const size_t o0 = (size_t)blockIdx.x * 512;
    oh[o0 + t]       = __float2half_rn(e0 * inv);
    oh[o0 + t + 256] = __float2half_rn(e1 * inv);
}

// ---------------------------------------------------------------------------
extern "C" void kernel_launch(void* const* d_in, const int* in_sizes, int n_in,
                              void* d_out, int out_size)
{
    const float* P = (const float*)d_in[0];
    const float* H = (const float*)d_in[1];
    const float* W = (const float*)d_in[2];
    float* out = (float*)d_out;   // [betas ; alphas]

    __half *Xh,*Xl,*Fh_,*Fl_,*ah,*Wth,*Wtl;
    float* lg;
    cudaGetSymbolAddress((void**)&Xh, g_Xh);   cudaGetSymbolAddress((void**)&Xl, g_Xl);
    cudaGetSymbolAddress((void**)&Fh_, g_Fh_); cudaGetSymbolAddress((void**)&Fl_, g_Fl_);
    cudaGetSymbolAddress((void**)&ah, g_ah);
    cudaGetSymbolAddress((void**)&Wth, g_Wth); cudaGetSymbolAddress((void**)&Wtl, g_Wtl);
    cudaGetSymbolAddress((void**)&lg, g_logits);

    cudaFuncSetAttribute(gemm_mma<1>, cudaFuncAttributeMaxDynamicSharedMemorySize, SMEM_DYN);
    cudaFuncSetAttribute(gemm_mma<0>, cudaFuncAttributeMaxDynamicSharedMemorySize, SMEM_DYN);
    cudaFuncSetAttribute(gemm_out<0>, cudaFuncAttributeMaxDynamicSharedMemorySize, OSMEM);
    cudaFuncSetAttribute(gemm_out<1>, cudaFuncAttributeMaxDynamicSharedMemorySize, OSMEM);

    dim3 b256(256);

    // 1. splits: [P;H] natural hi/lo (streaming); W transposed hi/lo.
    split2<<<(unsigned)(2 * NTOT / 1024), b256>>>(P, H, Xh, Xl);
    splitT<<<dim3(16, 16, 1), b256>>>(W, Wth, Wtl);

    // 2. merged projection: [Fp;Fh] = tanh([P;H] @ W), M = 65536, 3-term
    gemm_mma<1><<<dim3(4, 512, 1), b256, SMEM_DYN>>>(Xh, Xl, Wth, Wtl, 0, 0,
                                                     nullptr, 0, Fh_, Fl_);

    // 3. logits = F_p @ F_h^T per batch, 3-term
    gemm_mma<0><<<dim3(4, 4, BB), b256, SMEM_DYN>>>(Fh_, Fl_, Fh_ + NTOT, Fl_ + NTOT,
                                                    512, 512, lg, (long)512 * 512,
                                                    nullptr, nullptr);

    // 4. softmax -> attn hi (natural only; no transposed copy needed)
    softmax_h<<<BB * LL, b256>>>(lg, ah);

    // 5. betas = attn @ H (B trans-loaded from natural H hi)
    gemm_out<0><<<dim3(4, 4, BB), b256, OSMEM>>>(ah, Xh + NTOT, out);
    //    alphas = attn^T @ P (A trans-loaded from natural attn, B from natural P hi)
    gemm_out<1><<<dim3(4, 4, BB), b256, OSMEM>>>(ah, Xh, out + NTOT);
}